// round 5
// baseline (speedup 1.0000x reference)
#include <cuda_runtime.h>
#include <cstddef>

// ---------------------------------------------------------------------------
// Problem constants (fixed by the reference setup): B=4, S=8192, D=512, H=8,
// HD=64, W=128.  MT = B*S = 32768 tokens, 256 windows of 128 tokens.
// ---------------------------------------------------------------------------
#define MT 32768
#define DD 512
#define D3 1536
#define DF 2048

// Scratch (device globals — allocation-free per harness rules)
__device__ float g_qkv[(size_t)MT * D3];   // 192 MB
__device__ float g_attn[(size_t)MT * DD];  //  64 MB
__device__ float g_x1[(size_t)MT * DD];    //  64 MB
__device__ float g_resb[(size_t)MT * DD];  //  64 MB
__device__ float g_ff[(size_t)MT * DF];    // 256 MB

// ---------------------------------------------------------------------------
// Packed fp32x2 helpers (Blackwell FFMA2 — only reachable from PTX)
// ---------------------------------------------------------------------------
__device__ __forceinline__ unsigned long long pack2(float lo, float hi) {
    unsigned long long r;
    asm("mov.b64 %0, {%1, %2};" : "=l"(r) : "f"(lo), "f"(hi));
    return r;
}
__device__ __forceinline__ void unpack2(unsigned long long v, float &lo, float &hi) {
    asm("mov.b64 {%0, %1}, %2;" : "=f"(lo), "=f"(hi) : "l"(v));
}
__device__ __forceinline__ void ffma2(unsigned long long &d,
                                      unsigned long long a,
                                      unsigned long long b) {
    asm("fma.rn.f32x2 %0, %1, %2, %0;" : "+l"(d) : "l"(a), "l"(b));
}

// ---------------------------------------------------------------------------
// Generic GEMM: C[m,n] = sum_k A[m,k]*B[n,k] + bias[n]  (both inputs K-major)
//   EPI 0: bias only
//   EPI 1: bias + ReLU
//   EPI 2: bias + residual add (res[m,n])
// BM=BN=128, BK=8, 256 threads, 8x8 per thread, double-buffered smem,
// inner loop = 32x fma.rn.f32x2 per k-step (M-dim packed pairs).
// All problem dims divide the tile sizes — no bounds checks.
// ---------------------------------------------------------------------------
template <int EPI>
__global__ void __launch_bounds__(256)
gemm_kernel(const float* __restrict__ A, const float* __restrict__ B,
            const float* __restrict__ bias, const float* __restrict__ res,
            float* __restrict__ C, int N, int K)
{
    __shared__ float As[2][8][128];
    __shared__ float Bs[2][8][128];

    const int tid = threadIdx.x;
    const int tx  = tid & 15;        // n direction (16)
    const int ty  = tid >> 4;        // m direction (16)
    const int m0  = blockIdx.y * 128;
    const int n0  = blockIdx.x * 128;
    const int tm  = ty * 8;
    const int tn  = tx * 8;

    // global-load mapping: 256 threads -> 128 rows x 2 float4 (k 0..7)
    const int lr = tid >> 1;
    const int lk = (tid & 1) * 4;
    const float* Ag = A + (size_t)(m0 + lr) * K + lk;
    const float* Bg = B + (size_t)(n0 + lr) * K + lk;

    unsigned long long acc[4][8];
#pragma unroll
    for (int i = 0; i < 4; i++)
#pragma unroll
        for (int j = 0; j < 8; j++) acc[i][j] = 0ull;

    // preload tile 0
    {
        float4 av = *(const float4*)Ag;
        float4 bv = *(const float4*)Bg;
        As[0][lk + 0][lr] = av.x; As[0][lk + 1][lr] = av.y;
        As[0][lk + 2][lr] = av.z; As[0][lk + 3][lr] = av.w;
        Bs[0][lk + 0][lr] = bv.x; Bs[0][lk + 1][lr] = bv.y;
        Bs[0][lk + 2][lr] = bv.z; Bs[0][lk + 3][lr] = bv.w;
    }
    __syncthreads();

    const int nk = K >> 3;
    for (int kt = 0; kt < nk; kt++) {
        const int cur = kt & 1;
        float4 av, bv;
        if (kt + 1 < nk) {
            av = *(const float4*)(Ag + (size_t)(kt + 1) * 8);
            bv = *(const float4*)(Bg + (size_t)(kt + 1) * 8);
        }
#pragma unroll
        for (int kk = 0; kk < 8; kk++) {
            float4 a0 = *(const float4*)&As[cur][kk][tm];
            float4 a1 = *(const float4*)&As[cur][kk][tm + 4];
            float4 b0 = *(const float4*)&Bs[cur][kk][tn];
            float4 b1 = *(const float4*)&Bs[cur][kk][tn + 4];
            unsigned long long ap[4] = {
                pack2(a0.x, a0.y), pack2(a0.z, a0.w),
                pack2(a1.x, a1.y), pack2(a1.z, a1.w)
            };
            float bf[8] = {b0.x, b0.y, b0.z, b0.w, b1.x, b1.y, b1.z, b1.w};
#pragma unroll
            for (int j = 0; j < 8; j++) {
                unsigned long long bp = pack2(bf[j], bf[j]);
#pragma unroll
                for (int i = 0; i < 4; i++) ffma2(acc[i][j], ap[i], bp);
            }
        }
        if (kt + 1 < nk) {
            const int nxt = cur ^ 1;
            As[nxt][lk + 0][lr] = av.x; As[nxt][lk + 1][lr] = av.y;
            As[nxt][lk + 2][lr] = av.z; As[nxt][lk + 3][lr] = av.w;
            Bs[nxt][lk + 0][lr] = bv.x; Bs[nxt][lk + 1][lr] = bv.y;
            Bs[nxt][lk + 2][lr] = bv.z; Bs[nxt][lk + 3][lr] = bv.w;
        }
        __syncthreads();
    }

    // epilogue: unpack m-paired accumulators into row-major register tile
    float cr[8][8];
#pragma unroll
    for (int i = 0; i < 4; i++)
#pragma unroll
        for (int j = 0; j < 8; j++)
            unpack2(acc[i][j], cr[2 * i][j], cr[2 * i + 1][j]);

    float4 bv0 = *(const float4*)(bias + n0 + tn);
    float4 bv1 = *(const float4*)(bias + n0 + tn + 4);
    const float bb[8] = {bv0.x, bv0.y, bv0.z, bv0.w, bv1.x, bv1.y, bv1.z, bv1.w};

#pragma unroll
    for (int i = 0; i < 8; i++) {
        const size_t off = (size_t)(m0 + tm + i) * N + n0 + tn;
        float v[8];
#pragma unroll
        for (int j = 0; j < 8; j++) v[j] = cr[i][j] + bb[j];
        if (EPI == 1) {
#pragma unroll
            for (int j = 0; j < 8; j++) v[j] = fmaxf(v[j], 0.0f);
        }
        if (EPI == 2) {
            float4 r0 = *(const float4*)(res + off);
            float4 r1 = *(const float4*)(res + off + 4);
            v[0] += r0.x; v[1] += r0.y; v[2] += r0.z; v[3] += r0.w;
            v[4] += r1.x; v[5] += r1.y; v[6] += r1.z; v[7] += r1.w;
        }
        *(float4*)(C + off)     = make_float4(v[0], v[1], v[2], v[3]);
        *(float4*)(C + off + 4) = make_float4(v[4], v[5], v[6], v[7]);
    }
}

// ---------------------------------------------------------------------------
// Windowed multi-head attention.
// Grid (256 windows, 8 heads), 128 threads (one query row per thread).
// Dynamic smem: K[128][65], V[128][65], S[128][129]  -> 132,608 bytes.
// ---------------------------------------------------------------------------
#define KV_STR 65
#define S_STR  129
#define ATTN_SMEM_BYTES ((2 * 128 * KV_STR + 128 * S_STR) * (int)sizeof(float))

__global__ void __launch_bounds__(128)
attn_kernel(const float* __restrict__ qkv, float* __restrict__ out)
{
    extern __shared__ float sm[];
    float* Ks = sm;
    float* Vs = sm + 128 * KV_STR;
    float* Ss = sm + 2 * 128 * KV_STR;

    const int tid = threadIdx.x;
    const int win = blockIdx.x;
    const int h   = blockIdx.y;
    const size_t base = (size_t)win * 128 * D3 + h * 64;
    const float* kg = qkv + base + 512;
    const float* vg = qkv + base + 1024;

    // cooperative, coalesced K/V load (16 float4 per thread each)
#pragma unroll
    for (int it = 0; it < 16; it++) {
        int idx = it * 128 + tid;       // 0..2047
        int row = idx >> 4;
        int c   = (idx & 15) * 4;
        float4 kv = *(const float4*)(kg + (size_t)row * D3 + c);
        float4 vv = *(const float4*)(vg + (size_t)row * D3 + c);
        float* kd = Ks + row * KV_STR + c;
        kd[0] = kv.x; kd[1] = kv.y; kd[2] = kv.z; kd[3] = kv.w;
        float* vd = Vs + row * KV_STR + c;
        vd[0] = vv.x; vd[1] = vv.y; vd[2] = vv.z; vd[3] = vv.w;
    }

    // this thread's q row into registers
    float q[64];
    const float* qg = qkv + base + (size_t)tid * D3;
#pragma unroll
    for (int i = 0; i < 16; i++) {
        float4 v = *(const float4*)(qg + 4 * i);
        q[4 * i] = v.x; q[4 * i + 1] = v.y; q[4 * i + 2] = v.z; q[4 * i + 3] = v.w;
    }
    __syncthreads();

    // scores (broadcast LDS over K rows), row-max
    float* srow = Ss + tid * S_STR;
    float mx = -1e30f;
    for (int j = 0; j < 128; j++) {
        const float* kr = Ks + j * KV_STR;
        float s0 = 0.f, s1 = 0.f, s2 = 0.f, s3 = 0.f;
#pragma unroll
        for (int d = 0; d < 64; d += 4) {
            s0 += q[d]     * kr[d];
            s1 += q[d + 1] * kr[d + 1];
            s2 += q[d + 2] * kr[d + 2];
            s3 += q[d + 3] * kr[d + 3];
        }
        float s = (s0 + s1 + s2 + s3) * 0.125f;   // / sqrt(64)
        srow[j] = s;
        mx = fmaxf(mx, s);
    }
    float sum = 0.f;
    for (int j = 0; j < 128; j++) {
        float e = __expf(srow[j] - mx);
        srow[j] = e;
        sum += e;
    }
    const float inv = 1.0f / sum;

    // O = P V  (broadcast LDS over V rows, 64 independent accumulators)
    float o[64];
#pragma unroll
    for (int d = 0; d < 64; d++) o[d] = 0.f;
    for (int j = 0; j < 128; j++) {
        float p = srow[j];
        const float* vr = Vs + j * KV_STR;
#pragma unroll
        for (int d = 0; d < 64; d++) o[d] += p * vr[d];
    }

    float* og = out + ((size_t)win * 128 + tid) * DD + h * 64;
#pragma unroll
    for (int i = 0; i < 16; i++) {
        *(float4*)(og + 4 * i) = make_float4(o[4 * i] * inv, o[4 * i + 1] * inv,
                                             o[4 * i + 2] * inv, o[4 * i + 3] * inv);
    }
}

// ---------------------------------------------------------------------------
// LayerNorm over D=512. One row per 128-thread block, 4 elements per thread,
// exact two-pass (mean then centered sum-of-squares).
// ---------------------------------------------------------------------------
__global__ void __launch_bounds__(128)
ln_kernel(const float* __restrict__ x, const float* __restrict__ g,
          const float* __restrict__ b, float* __restrict__ out)
{
    __shared__ float red[8];
    const int row = blockIdx.x;
    const int tid = threadIdx.x;
    const int lane = tid & 31, wid = tid >> 5;

    float4 v = *(const float4*)(x + (size_t)row * DD + tid * 4);
    float s = v.x + v.y + v.z + v.w;
#pragma unroll
    for (int o = 16; o > 0; o >>= 1) s += __shfl_xor_sync(0xffffffffu, s, o);
    if (lane == 0) red[wid] = s;
    __syncthreads();
    if (tid == 0) red[0] = red[0] + red[1] + red[2] + red[3];
    __syncthreads();
    const float mu = red[0] * (1.0f / 512.0f);

    const float d0 = v.x - mu, d1 = v.y - mu, d2 = v.z - mu, d3 = v.w - mu;
    float sq = d0 * d0 + d1 * d1 + d2 * d2 + d3 * d3;
#pragma unroll
    for (int o = 16; o > 0; o >>= 1) sq += __shfl_xor_sync(0xffffffffu, sq, o);
    __syncthreads();                  // everyone has consumed red[0]
    if (lane == 0) red[wid] = sq;
    __syncthreads();
    if (tid == 0) red[0] = red[0] + red[1] + red[2] + red[3];
    __syncthreads();
    const float inv = rsqrtf(red[0] * (1.0f / 512.0f) + 1e-5f);

    float4 gg = *(const float4*)(g + tid * 4);
    float4 bb = *(const float4*)(b + tid * 4);
    *(float4*)(out + (size_t)row * DD + tid * 4) =
        make_float4(d0 * inv * gg.x + bb.x, d1 * inv * gg.y + bb.y,
                    d2 * inv * gg.z + bb.z, d3 * inv * gg.w + bb.w);
}

// ---------------------------------------------------------------------------
// Launch pipeline (graph-capturable: kernel launches + attr/symbol queries only)
// ---------------------------------------------------------------------------
extern "C" void kernel_launch(void* const* d_in, const int* in_sizes, int n_in,
                              void* d_out, int out_size)
{
    (void)in_sizes; (void)n_in; (void)out_size;
    const float* src   = (const float*)d_in[0];
    const float* wqkv  = (const float*)d_in[1];
    const float* bqkv  = (const float*)d_in[2];
    const float* wout  = (const float*)d_in[3];
    const float* bout  = (const float*)d_in[4];
    const float* ln1g  = (const float*)d_in[5];
    const float* ln1b  = (const float*)d_in[6];
    const float* w1    = (const float*)d_in[7];
    const float* b1    = (const float*)d_in[8];
    const float* w2    = (const float*)d_in[9];
    const float* b2    = (const float*)d_in[10];
    const float* ln2g  = (const float*)d_in[11];
    const float* ln2b  = (const float*)d_in[12];
    float* out = (float*)d_out;

    float *qkv, *attn, *x1, *resb, *ff;
    cudaGetSymbolAddress((void**)&qkv,  g_qkv);
    cudaGetSymbolAddress((void**)&attn, g_attn);
    cudaGetSymbolAddress((void**)&x1,   g_x1);
    cudaGetSymbolAddress((void**)&resb, g_resb);
    cudaGetSymbolAddress((void**)&ff,   g_ff);

    cudaFuncSetAttribute(attn_kernel,
                         cudaFuncAttributeMaxDynamicSharedMemorySize,
                         ATTN_SMEM_BYTES);

    // 1) QKV projection: [MT,512] x [1536,512]^T -> [MT,1536]
    gemm_kernel<0><<<dim3(D3 / 128, MT / 128), 256>>>(src, wqkv, bqkv, nullptr,
                                                      qkv, D3, DD);
    // 2) windowed attention -> [MT,512]
    attn_kernel<<<dim3(MT / 128, 8), 128, ATTN_SMEM_BYTES>>>(qkv, attn);
    // 3) out projection + residual(src) -> resb
    gemm_kernel<2><<<dim3(DD / 128, MT / 128), 256>>>(attn, wout, bout, src,
                                                      resb, DD, DD);
    // 4) LayerNorm 1 -> x1
    ln_kernel<<<MT, 128>>>(resb, ln1g, ln1b, x1);
    // 5) FFN up + ReLU: [MT,512] x [2048,512]^T -> [MT,2048]
    gemm_kernel<1><<<dim3(DF / 128, MT / 128), 256>>>(x1, w1, b1, nullptr,
                                                      ff, DF, DD);
    // 6) FFN down + residual(x1) -> resb
    gemm_kernel<2><<<dim3(DD / 128, MT / 128), 256>>>(ff, w2, b2, x1,
                                                      resb, DD, DF);
    // 7) LayerNorm 2 -> output
    ln_kernel<<<MT, 128>>>(resb, ln2g, ln2b, out);
}

// round 9
// speedup vs baseline: 2.1529x; 2.1529x over previous
#include <cuda_runtime.h>
#include <cuda_bf16.h>
#include <cstddef>
#include <cstdint>

// ---------------------------------------------------------------------------
// Problem constants: B=4, S=8192, D=512, H=8, HD=64, W=128.
// MT = 32768 tokens, 256 windows of 128.
// ---------------------------------------------------------------------------
#define MT 32768
#define DD 512
#define D3 1536
#define DF 2048

// ---------------------------------------------------------------------------
// Scratch (device globals — allocation-free per harness rules)
// ---------------------------------------------------------------------------
__device__ float g_qkv [(size_t)MT * D3];     // f32 qkv for attention
__device__ float g_x1  [(size_t)MT * DD];     // f32 ln1 output (residual for FFN)
__device__ float g_resb[(size_t)MT * DD];     // f32 pre-LN buffer

// hi/lo bf16 planes (bf16x3 GEMM operands)
__device__ __nv_bfloat16 g_sh [(size_t)MT * DD], g_sl [(size_t)MT * DD];   // src
__device__ __nv_bfloat16 g_ah [(size_t)MT * DD], g_al [(size_t)MT * DD];   // attn out
__device__ __nv_bfloat16 g_xh [(size_t)MT * DD], g_xl [(size_t)MT * DD];   // ln1 out
__device__ __nv_bfloat16 g_fh [(size_t)MT * DF], g_fl [(size_t)MT * DF];   // ffn mid
__device__ __nv_bfloat16 g_wqh[D3 * DD], g_wql[D3 * DD];
__device__ __nv_bfloat16 g_woh[DD * DD], g_wol[DD * DD];
__device__ __nv_bfloat16 g_w1h[DF * DD], g_w1l[DF * DD];
__device__ __nv_bfloat16 g_w2h[DD * DF], g_w2l[DD * DF];

// ---------------------------------------------------------------------------
// PTX helpers (plain-compute_103 features: cp.async / ldmatrix / mma.sync)
// ---------------------------------------------------------------------------
__device__ __forceinline__ uint32_t cvta_s(const void* p) {
    uint32_t a;
    asm("{ .reg .u64 t; cvta.to.shared.u64 t, %1; cvt.u32.u64 %0, t; }"
        : "=r"(a) : "l"(p));
    return a;
}
__device__ __forceinline__ void cp16(uint32_t dst, const void* src) {
    asm volatile("cp.async.cg.shared.global [%0], [%1], 16;"
                 :: "r"(dst), "l"(src));
}
__device__ __forceinline__ void ldsm_x4(uint32_t* r, uint32_t addr) {
    asm volatile("ldmatrix.sync.aligned.m8n8.x4.shared.b16 {%0,%1,%2,%3}, [%4];"
                 : "=r"(r[0]), "=r"(r[1]), "=r"(r[2]), "=r"(r[3]) : "r"(addr));
}
__device__ __forceinline__ void mma_bf16(float* d, const uint32_t* a,
                                         const uint32_t* b) {
    asm volatile(
        "mma.sync.aligned.m16n8k16.row.col.f32.bf16.bf16.f32 "
        "{%0,%1,%2,%3}, {%4,%5,%6,%7}, {%8,%9}, {%0,%1,%2,%3};"
        : "+f"(d[0]), "+f"(d[1]), "+f"(d[2]), "+f"(d[3])
        : "r"(a[0]), "r"(a[1]), "r"(a[2]), "r"(a[3]), "r"(b[0]), "r"(b[1]));
}

// fp32 -> (hi,lo) bf16 split, packed 2-wide into u32s
__device__ __forceinline__ void split2(float a, float b, uint32_t& h, uint32_t& l) {
    __nv_bfloat16 ha = __float2bfloat16(a);
    __nv_bfloat16 hb = __float2bfloat16(b);
    __nv_bfloat16 la = __float2bfloat16(a - __bfloat162float(ha));
    __nv_bfloat16 lb = __float2bfloat16(b - __bfloat162float(hb));
    h = (uint32_t)__bfloat16_as_ushort(ha) | ((uint32_t)__bfloat16_as_ushort(hb) << 16);
    l = (uint32_t)__bfloat16_as_ushort(la) | ((uint32_t)__bfloat16_as_ushort(lb) << 16);
}

// ---------------------------------------------------------------------------
// HMMA bf16x3 GEMM: C[m,n] = sum_k A[m,k]*B[n,k] + bias[n] (+ epilogue)
//   A,B as hi/lo bf16 planes, both K-major (so BOTH operands use non-trans
//   ldmatrix: mma .row.col B fragment = consecutive-k pairs at fixed n, which
//   is exactly what non-trans ldmatrix yields on an [n][k] tile).
//   CTA tile 128x128, BK=64 (128B rows, XOR-swizzled), 2-stage cp.async,
//   8 warps (2M x 4N), warp tile 64x32, 3 products (AhBh, AhBl, AlBh).
//   EPI 0: bias -> f32 out
//   EPI 1: bias + ReLU -> hi/lo bf16 planes
//   EPI 2: bias + f32 residual -> f32 out
// ---------------------------------------------------------------------------
static constexpr int STAGE = 65536;   // Ah 16K | Al 16K | Bh 16K | Bl 16K

__device__ __forceinline__ void load_chunk(
    const __nv_bfloat16* __restrict__ Ah, const __nv_bfloat16* __restrict__ Al,
    const __nv_bfloat16* __restrict__ Bh, const __nv_bfloat16* __restrict__ Bl,
    int m0, int n0, int K, int k0, int tid, uint32_t sb)
{
#pragma unroll
    for (int j = 0; j < 4; j++) {
        int id  = tid + 256 * j;          // 0..1023
        int row = id >> 3;                // 0..127
        int c   = id & 7;                 // 16B chunk within 128B row
        uint32_t soff = (uint32_t)(row * 128 + ((c ^ (row & 7)) << 4));
        size_t ga = (size_t)(m0 + row) * K + k0 + c * 8;
        size_t gb = (size_t)(n0 + row) * K + k0 + c * 8;
        cp16(sb + soff,          Ah + ga);
        cp16(sb + 16384 + soff,  Al + ga);
        cp16(sb + 32768 + soff,  Bh + gb);
        cp16(sb + 49152 + soff,  Bl + gb);
    }
    asm volatile("cp.async.commit_group;" ::: "memory");
}

template <int EPI>
__global__ void __launch_bounds__(256)
tc_gemm(const __nv_bfloat16* __restrict__ Ah, const __nv_bfloat16* __restrict__ Al,
        const __nv_bfloat16* __restrict__ Bh, const __nv_bfloat16* __restrict__ Bl,
        const float* __restrict__ bias, const float* __restrict__ res,
        float* __restrict__ Cf,
        __nv_bfloat16* __restrict__ Ch, __nv_bfloat16* __restrict__ Cl,
        int N, int K)
{
    extern __shared__ __align__(1024) char dyn_smem[];
    uint32_t sbase = (cvta_s(dyn_smem) + 1023u) & ~1023u;

    const int tid  = threadIdx.x;
    const int lane = tid & 31;
    const int w    = tid >> 5;
    const int wm   = w & 1;               // 0..1  (M)
    const int wn   = w >> 1;              // 0..3  (N)
    const int m0   = blockIdx.y * 128;
    const int n0   = blockIdx.x * 128;

    float acc[4][4][4];
#pragma unroll
    for (int i = 0; i < 4; i++)
#pragma unroll
        for (int j = 0; j < 4; j++)
#pragma unroll
            for (int c = 0; c < 4; c++) acc[i][j][c] = 0.0f;

    const int nk = K >> 6;
    load_chunk(Ah, Al, Bh, Bl, m0, n0, K, 0, tid, sbase);

    // ldmatrix lane->address maps (constant across k-chunks)
    // A (x4): lanes 0-15 -> rows m0..m15 (k-half 0), lanes 16-31 -> same rows (k-half 1)
    const int am   = wm * 64 + (lane & 15);                       // + mt*16
    const int acb  = (lane >> 4);                                 // k-half
    // B (x4): lanes 0-7 n0-7/k-half0, 8-15 n0-7/k-half1, 16-23 n8-15/k0, 24-31 n8-15/k1
    const int bn   = wn * 32 + (lane & 7) + ((lane >> 4) << 3);   // + bt*16
    const int bcb  = (lane >> 3) & 1;

    for (int i = 0; i < nk; i++) {
        if (i + 1 < nk) {
            load_chunk(Ah, Al, Bh, Bl, m0, n0, K, (i + 1) << 6, tid,
                       sbase + (uint32_t)((i + 1) & 1) * STAGE);
            asm volatile("cp.async.wait_group 1;" ::: "memory");
        } else {
            asm volatile("cp.async.wait_group 0;" ::: "memory");
        }
        __syncthreads();

        const uint32_t sA  = sbase + (uint32_t)(i & 1) * STAGE;
        const uint32_t sAl = sA + 16384;
        const uint32_t sB  = sA + 32768;
        const uint32_t sBl = sA + 49152;

#pragma unroll
        for (int ks = 0; ks < 4; ks++) {
            uint32_t ahf[4][4], alf[4][4];
#pragma unroll
            for (int mt = 0; mt < 4; mt++) {
                int m = am + mt * 16;
                int c = ks * 2 + acb;
                uint32_t off = (uint32_t)(m * 128 + ((c ^ (m & 7)) << 4));
                ldsm_x4(ahf[mt], sA  + off);
                ldsm_x4(alf[mt], sAl + off);
            }
            uint32_t bhf[2][4], blf[2][4];
#pragma unroll
            for (int bt = 0; bt < 2; bt++) {
                int n = bn + bt * 16;
                int c = ks * 2 + bcb;
                uint32_t off = (uint32_t)(n * 128 + ((c ^ (n & 7)) << 4));
                ldsm_x4(bhf[bt], sB  + off);    // NON-trans: [n][k] == A layout
                ldsm_x4(blf[bt], sBl + off);
            }
#pragma unroll
            for (int mt = 0; mt < 4; mt++)
#pragma unroll
                for (int nt = 0; nt < 4; nt++) {
                    const uint32_t* ph = &bhf[nt >> 1][(nt & 1) * 2];
                    const uint32_t* pl = &blf[nt >> 1][(nt & 1) * 2];
                    mma_bf16(acc[mt][nt], ahf[mt], ph);
                    mma_bf16(acc[mt][nt], ahf[mt], pl);
                    mma_bf16(acc[mt][nt], alf[mt], ph);
                }
        }
        __syncthreads();
    }

    // ---- epilogue: c fragment: c0=(g,2t) c1=(g,2t+1) c2=(g+8,2t) c3=(g+8,2t+1)
    const int gq = lane >> 2;
    const int tq = lane & 3;
#pragma unroll
    for (int mt = 0; mt < 4; mt++)
#pragma unroll
        for (int nt = 0; nt < 4; nt++) {
            const int n  = n0 + wn * 32 + nt * 8 + tq * 2;
            const float b0 = bias[n], b1 = bias[n + 1];
#pragma unroll
            for (int half = 0; half < 2; half++) {
                const int m  = m0 + wm * 64 + mt * 16 + gq + half * 8;
                float v0 = acc[mt][nt][half * 2 + 0] + b0;
                float v1 = acc[mt][nt][half * 2 + 1] + b1;
                const size_t off = (size_t)m * N + n;
                if (EPI == 2) {
                    float2 r2 = *(const float2*)(res + off);
                    v0 += r2.x; v1 += r2.y;
                }
                if (EPI == 1) {
                    v0 = fmaxf(v0, 0.0f); v1 = fmaxf(v1, 0.0f);
                    uint32_t hu, lu;
                    split2(v0, v1, hu, lu);
                    *(uint32_t*)(Ch + off) = hu;
                    *(uint32_t*)(Cl + off) = lu;
                } else {
                    *(float2*)(Cf + off) = make_float2(v0, v1);
                }
            }
        }
}

// ---------------------------------------------------------------------------
// f32 -> hi/lo bf16 plane conversion (4 elems/thread)
// ---------------------------------------------------------------------------
__global__ void __launch_bounds__(256)
cvt_kernel(const float* __restrict__ x, __nv_bfloat16* __restrict__ hi,
           __nv_bfloat16* __restrict__ lo, int n4)
{
    int i = blockIdx.x * 256 + threadIdx.x;
    if (i >= n4) return;
    float4 v = ((const float4*)x)[i];
    uint32_t h0, l0, h1, l1;
    split2(v.x, v.y, h0, l0);
    split2(v.z, v.w, h1, l1);
    ((uint2*)hi)[i] = make_uint2(h0, h1);
    ((uint2*)lo)[i] = make_uint2(l0, l1);
}

// ---------------------------------------------------------------------------
// Windowed attention: grid (256 windows, 8 heads), 128 threads (1 q-row each).
// Reads f32 qkv, writes hi/lo bf16 planes (next GEMM's A operand).
// ---------------------------------------------------------------------------
#define KV_STR 65
#define S_STR  129
#define ATTN_SMEM_BYTES ((2 * 128 * KV_STR + 128 * S_STR) * (int)sizeof(float))

__global__ void __launch_bounds__(128)
attn_kernel(const float* __restrict__ qkv,
            __nv_bfloat16* __restrict__ oh, __nv_bfloat16* __restrict__ ol)
{
    extern __shared__ float sm[];
    float* Ks = sm;
    float* Vs = sm + 128 * KV_STR;
    float* Ss = sm + 2 * 128 * KV_STR;

    const int tid = threadIdx.x;
    const int win = blockIdx.x;
    const int h   = blockIdx.y;
    const size_t base = (size_t)win * 128 * D3 + h * 64;
    const float* kg = qkv + base + 512;
    const float* vg = qkv + base + 1024;

#pragma unroll
    for (int it = 0; it < 16; it++) {
        int idx = it * 128 + tid;
        int row = idx >> 4;
        int c   = (idx & 15) * 4;
        float4 kv = *(const float4*)(kg + (size_t)row * D3 + c);
        float4 vv = *(const float4*)(vg + (size_t)row * D3 + c);
        float* kd = Ks + row * KV_STR + c;
        kd[0] = kv.x; kd[1] = kv.y; kd[2] = kv.z; kd[3] = kv.w;
        float* vd = Vs + row * KV_STR + c;
        vd[0] = vv.x; vd[1] = vv.y; vd[2] = vv.z; vd[3] = vv.w;
    }

    float q[64];
    const float* qg = qkv + base + (size_t)tid * D3;
#pragma unroll
    for (int i = 0; i < 16; i++) {
        float4 v = *(const float4*)(qg + 4 * i);
        q[4*i] = v.x; q[4*i+1] = v.y; q[4*i+2] = v.z; q[4*i+3] = v.w;
    }
    __syncthreads();

    float* srow = Ss + tid * S_STR;
    float mx = -1e30f;
    for (int j = 0; j < 128; j++) {
        const float* kr = Ks + j * KV_STR;
        float s0 = 0.f, s1 = 0.f, s2 = 0.f, s3 = 0.f;
#pragma unroll
        for (int d = 0; d < 64; d += 4) {
            s0 += q[d]     * kr[d];
            s1 += q[d + 1] * kr[d + 1];
            s2 += q[d + 2] * kr[d + 2];
            s3 += q[d + 3] * kr[d + 3];
        }
        float s = (s0 + s1 + s2 + s3) * 0.125f;
        srow[j] = s;
        mx = fmaxf(mx, s);
    }
    float sum = 0.f;
    for (int j = 0; j < 128; j++) {
        float e = __expf(srow[j] - mx);
        srow[j] = e;
        sum += e;
    }
    const float inv = 1.0f / sum;

    float o[64];
#pragma unroll
    for (int d = 0; d < 64; d++) o[d] = 0.f;
    for (int j = 0; j < 128; j++) {
        float p = srow[j];
        const float* vr = Vs + j * KV_STR;
#pragma unroll
        for (int d = 0; d < 64; d++) o[d] += p * vr[d];
    }

    const size_t ob = ((size_t)win * 128 + tid) * DD + h * 64;
#pragma unroll
    for (int qd = 0; qd < 16; qd++) {
        uint32_t h0, l0, h1, l1;
        split2(o[4*qd]   * inv, o[4*qd+1] * inv, h0, l0);
        split2(o[4*qd+2] * inv, o[4*qd+3] * inv, h1, l1);
        ((uint2*)(oh + ob))[qd] = make_uint2(h0, h1);
        ((uint2*)(ol + ob))[qd] = make_uint2(l0, l1);
    }
}

// ---------------------------------------------------------------------------
// LayerNorm over D=512 (1 row per 128-thread block).  HL=true also emits
// hi/lo bf16 planes for the following GEMM.
// ---------------------------------------------------------------------------
template <bool HL>
__global__ void __launch_bounds__(128)
ln_kernel(const float* __restrict__ x, const float* __restrict__ g,
          const float* __restrict__ b, float* __restrict__ outf,
          __nv_bfloat16* __restrict__ oh, __nv_bfloat16* __restrict__ ol)
{
    __shared__ float red[8];
    const int row = blockIdx.x;
    const int tid = threadIdx.x;
    const int lane = tid & 31, wid = tid >> 5;

    float4 v = *(const float4*)(x + (size_t)row * DD + tid * 4);
    float s = v.x + v.y + v.z + v.w;
#pragma unroll
    for (int o = 16; o > 0; o >>= 1) s += __shfl_xor_sync(0xffffffffu, s, o);
    if (lane == 0) red[wid] = s;
    __syncthreads();
    if (tid == 0) red[0] = red[0] + red[1] + red[2] + red[3];
    __syncthreads();
    const float mu = red[0] * (1.0f / 512.0f);

    const float d0 = v.x - mu, d1 = v.y - mu, d2 = v.z - mu, d3 = v.w - mu;
    float sq = d0*d0 + d1*d1 + d2*d2 + d3*d3;
#pragma unroll
    for (int o = 16; o > 0; o >>= 1) sq += __shfl_xor_sync(0xffffffffu, sq, o);
    __syncthreads();
    if (lane == 0) red[wid] = sq;
    __syncthreads();
    if (tid == 0) red[0] = red[0] + red[1] + red[2] + red[3];
    __syncthreads();
    const float inv = rsqrtf(red[0] * (1.0f / 512.0f) + 1e-5f);

    float4 gg = *(const float4*)(g + tid * 4);
    float4 bb = *(const float4*)(b + tid * 4);
    const float y0 = d0 * inv * gg.x + bb.x;
    const float y1 = d1 * inv * gg.y + bb.y;
    const float y2 = d2 * inv * gg.z + bb.z;
    const float y3 = d3 * inv * gg.w + bb.w;
    *(float4*)(outf + (size_t)row * DD + tid * 4) = make_float4(y0, y1, y2, y3);
    if (HL) {
        uint32_t h0, l0, h1, l1;
        split2(y0, y1, h0, l0);
        split2(y2, y3, h1, l1);
        const size_t i = (size_t)row * 128 + tid;
        ((uint2*)oh)[i] = make_uint2(h0, h1);
        ((uint2*)ol)[i] = make_uint2(l0, l1);
    }
}

// ---------------------------------------------------------------------------
// Launch pipeline (graph-capturable)
// ---------------------------------------------------------------------------
extern "C" void kernel_launch(void* const* d_in, const int* in_sizes, int n_in,
                              void* d_out, int out_size)
{
    (void)in_sizes; (void)n_in; (void)out_size;
    const float* src  = (const float*)d_in[0];
    const float* wqkv = (const float*)d_in[1];
    const float* bqkv = (const float*)d_in[2];
    const float* wout = (const float*)d_in[3];
    const float* bout = (const float*)d_in[4];
    const float* ln1g = (const float*)d_in[5];
    const float* ln1b = (const float*)d_in[6];
    const float* w1   = (const float*)d_in[7];
    const float* b1   = (const float*)d_in[8];
    const float* w2   = (const float*)d_in[9];
    const float* b2   = (const float*)d_in[10];
    const float* ln2g = (const float*)d_in[11];
    const float* ln2b = (const float*)d_in[12];
    float* out = (float*)d_out;

    float *qkv, *x1, *resb;
    __nv_bfloat16 *sh, *sl, *ah, *al, *xh, *xl, *fh, *fl;
    __nv_bfloat16 *wqh, *wql, *woh, *wol, *w1h, *w1l, *w2h, *w2l;
    cudaGetSymbolAddress((void**)&qkv,  g_qkv);
    cudaGetSymbolAddress((void**)&x1,   g_x1);
    cudaGetSymbolAddress((void**)&resb, g_resb);
    cudaGetSymbolAddress((void**)&sh,  g_sh);  cudaGetSymbolAddress((void**)&sl,  g_sl);
    cudaGetSymbolAddress((void**)&ah,  g_ah);  cudaGetSymbolAddress((void**)&al,  g_al);
    cudaGetSymbolAddress((void**)&xh,  g_xh);  cudaGetSymbolAddress((void**)&xl,  g_xl);
    cudaGetSymbolAddress((void**)&fh,  g_fh);  cudaGetSymbolAddress((void**)&fl,  g_fl);
    cudaGetSymbolAddress((void**)&wqh, g_wqh); cudaGetSymbolAddress((void**)&wql, g_wql);
    cudaGetSymbolAddress((void**)&woh, g_woh); cudaGetSymbolAddress((void**)&wol, g_wol);
    cudaGetSymbolAddress((void**)&w1h, g_w1h); cudaGetSymbolAddress((void**)&w1l, g_w1l);
    cudaGetSymbolAddress((void**)&w2h, g_w2h); cudaGetSymbolAddress((void**)&w2l, g_w2l);

    const int GEMM_SMEM = 2 * STAGE + 1024;
    cudaFuncSetAttribute(tc_gemm<0>, cudaFuncAttributeMaxDynamicSharedMemorySize, GEMM_SMEM);
    cudaFuncSetAttribute(tc_gemm<1>, cudaFuncAttributeMaxDynamicSharedMemorySize, GEMM_SMEM);
    cudaFuncSetAttribute(tc_gemm<2>, cudaFuncAttributeMaxDynamicSharedMemorySize, GEMM_SMEM);
    cudaFuncSetAttribute(attn_kernel, cudaFuncAttributeMaxDynamicSharedMemorySize, ATTN_SMEM_BYTES);

    // 0) hi/lo conversions: src + all weights
    cvt_kernel<<<(MT * DD / 4 + 255) / 256, 256>>>(src,  sh,  sl,  MT * DD / 4);
    cvt_kernel<<<(D3 * DD / 4 + 255) / 256, 256>>>(wqkv, wqh, wql, D3 * DD / 4);
    cvt_kernel<<<(DD * DD / 4 + 255) / 256, 256>>>(wout, woh, wol, DD * DD / 4);
    cvt_kernel<<<(DF * DD / 4 + 255) / 256, 256>>>(w1,   w1h, w1l, DF * DD / 4);
    cvt_kernel<<<(DD * DF / 4 + 255) / 256, 256>>>(w2,   w2h, w2l, DD * DF / 4);

    // 1) QKV projection -> f32 qkv
    tc_gemm<0><<<dim3(D3 / 128, MT / 128), 256, GEMM_SMEM>>>(
        sh, sl, wqh, wql, bqkv, nullptr, qkv, nullptr, nullptr, D3, DD);
    // 2) windowed attention -> attn hi/lo planes
    attn_kernel<<<dim3(MT / 128, 8), 128, ATTN_SMEM_BYTES>>>(qkv, ah, al);
    // 3) out projection + residual(src) -> resb f32
    tc_gemm<2><<<dim3(DD / 128, MT / 128), 256, GEMM_SMEM>>>(
        ah, al, woh, wol, bout, src, resb, nullptr, nullptr, DD, DD);
    // 4) LayerNorm 1 -> x1 f32 + hi/lo planes
    ln_kernel<true><<<MT, 128>>>(resb, ln1g, ln1b, x1, xh, xl);
    // 5) FFN up + ReLU -> ff hi/lo planes
    tc_gemm<1><<<dim3(DF / 128, MT / 128), 256, GEMM_SMEM>>>(
        xh, xl, w1h, w1l, b1, nullptr, nullptr, fh, fl, DF, DD);
    // 6) FFN down + residual(x1) -> resb f32
    tc_gemm<2><<<dim3(DD / 128, MT / 128), 256, GEMM_SMEM>>>(
        fh, fl, w2h, w2l, b2, x1, resb, nullptr, nullptr, DD, DF);
    // 7) LayerNorm 2 -> output
    ln_kernel<false><<<MT, 128>>>(resb, ln2g, ln2b, out, nullptr, nullptr);
}